// round 1
// baseline (speedup 1.0000x reference)
#include <cuda_runtime.h>
#include <math.h>

#define NN   50000
#define EE   800000
#define ET   (EE + NN)        // edges + self loops
#define FIN  128
#define HID  64
#define NEG_SLOPE 0.2f

// ---------------- scratch (device globals; no allocs allowed) ----------------
__device__ float g_h[NN * HID];        // x @ W
__device__ float g_asrc[NN];
__device__ float g_adst[NN];
__device__ int   g_count[NN];          // degree histogram
__device__ int   g_cursor[NN];         // scatter cursors (start offsets, mutated)
__device__ int   g_offsets[NN + 1];    // CSR offsets
__device__ int   g_srcs[ET];           // src node per CSR slot
__device__ float g_s0[NN];
__device__ float g_s1[NN];
__device__ int   g_is64;

// ---------------- dtype detection (int32 vs int64 edge_index) ----------------
__global__ void detect_kernel(const int* ew) {
    if (threadIdx.x == 0) {
        int all0 = 1;
        #pragma unroll 8
        for (int j = 0; j < 64; j++) {
            if (ew[2 * j + 1] != 0) { all0 = 0; break; }
        }
        g_is64 = all0;
    }
}

__device__ __forceinline__ int edge_at(const void* p, long long i, int is64) {
    return is64 ? (int)((const long long*)p)[i] : ((const int*)p)[i];
}

// ---------------- init ----------------
__global__ void zero_kernel() {
    int i = blockIdx.x * blockDim.x + threadIdx.x;
    if (i < NN) g_count[i] = 0;
}

// ---------------- GEMM: h = x @ W   (N x 128) @ (128 x 64) ----------------
// 32-row x 64-col tile per block, 128 threads, each thread 4x4 outputs.
__global__ void gemm_kernel(const float* __restrict__ x, const float* __restrict__ W) {
    __shared__ float xsT[FIN][32];   // transposed: [k][row]  16KB
    __shared__ float Ws[FIN][HID];   // [k][col]              32KB

    const int tid  = threadIdx.x;
    const int row0 = blockIdx.x * 32;
    const int tr   = tid >> 4;   // 0..7
    const int tc   = tid & 15;   // 0..15

    // load x tile (transposed into smem)
    #pragma unroll
    for (int it = 0; it < 8; it++) {
        int f  = it * 128 + tid;        // float4 id within 32x128 tile
        int r  = f >> 5;                // 0..31
        int k4 = f & 31;                // 0..31
        float4 v = make_float4(0.f, 0.f, 0.f, 0.f);
        if (row0 + r < NN)
            v = *(const float4*)&x[(long long)(row0 + r) * FIN + k4 * 4];
        xsT[k4 * 4 + 0][r] = v.x;
        xsT[k4 * 4 + 1][r] = v.y;
        xsT[k4 * 4 + 2][r] = v.z;
        xsT[k4 * 4 + 3][r] = v.w;
    }
    // load W (128x64)
    #pragma unroll
    for (int it = 0; it < 16; it++) {
        int f  = it * 128 + tid;        // float4 id within 128x64
        int kk = f >> 4;
        int c4 = f & 15;
        *(float4*)&Ws[kk][c4 * 4] = *(const float4*)&W[kk * HID + c4 * 4];
    }
    __syncthreads();

    float acc[4][4];
    #pragma unroll
    for (int i = 0; i < 4; i++)
        #pragma unroll
        for (int j = 0; j < 4; j++) acc[i][j] = 0.f;

    #pragma unroll 4
    for (int k = 0; k < FIN; k++) {
        float4 a = *(const float4*)&xsT[k][tr * 4];
        float4 b = *(const float4*)&Ws[k][tc * 4];
        acc[0][0] += a.x * b.x; acc[0][1] += a.x * b.y; acc[0][2] += a.x * b.z; acc[0][3] += a.x * b.w;
        acc[1][0] += a.y * b.x; acc[1][1] += a.y * b.y; acc[1][2] += a.y * b.z; acc[1][3] += a.y * b.w;
        acc[2][0] += a.z * b.x; acc[2][1] += a.z * b.y; acc[2][2] += a.z * b.z; acc[2][3] += a.z * b.w;
        acc[3][0] += a.w * b.x; acc[3][1] += a.w * b.y; acc[3][2] += a.w * b.z; acc[3][3] += a.w * b.w;
    }

    #pragma unroll
    for (int i = 0; i < 4; i++) {
        int r = row0 + tr * 4 + i;
        if (r < NN) {
            float4 v = make_float4(acc[i][0], acc[i][1], acc[i][2], acc[i][3]);
            *(float4*)&g_h[(long long)r * HID + tc * 4] = v;
        }
    }
}

// ---------------- per-node attention logits ----------------
// warp per row: a_src[n] = h[n]·att_src, a_dst[n] = h[n]·att_dst
__global__ void attn_kernel(const float* __restrict__ att_src, const float* __restrict__ att_dst) {
    int warp = (blockIdx.x * blockDim.x + threadIdx.x) >> 5;
    int lane = threadIdx.x & 31;
    if (warp >= NN) return;
    float v0 = g_h[warp * HID + lane];
    float v1 = g_h[warp * HID + 32 + lane];
    float pa = v0 * att_src[lane] + v1 * att_src[32 + lane];
    float pb = v0 * att_dst[lane] + v1 * att_dst[32 + lane];
    #pragma unroll
    for (int o = 16; o; o >>= 1) {
        pa += __shfl_xor_sync(0xffffffffu, pa, o);
        pb += __shfl_xor_sync(0xffffffffu, pb, o);
    }
    if (lane == 0) { g_asrc[warp] = pa; g_adst[warp] = pb; }
}

// ---------------- CSR build ----------------
__global__ void hist_kernel(const void* ei) {
    int i = blockIdx.x * blockDim.x + threadIdx.x;
    if (i >= ET) return;
    int is64 = g_is64;
    int dst = (i < EE) ? edge_at(ei, (long long)EE + i, is64) : (i - EE);
    atomicAdd(&g_count[dst], 1);
}

__global__ void scan_kernel() {
    __shared__ int sums[1024];
    const int CH = (NN + 1023) / 1024;   // 49
    int t = threadIdx.x;
    int base = t * CH;
    int s = 0;
    for (int j = 0; j < CH; j++) {
        int idx = base + j;
        if (idx < NN) s += g_count[idx];
    }
    sums[t] = s;
    __syncthreads();
    for (int off = 1; off < 1024; off <<= 1) {
        int v = (t >= off) ? sums[t - off] : 0;
        __syncthreads();
        sums[t] += v;
        __syncthreads();
    }
    int run = (t == 0) ? 0 : sums[t - 1];
    for (int j = 0; j < CH; j++) {
        int idx = base + j;
        if (idx < NN) {
            int c = g_count[idx];
            g_offsets[idx] = run;
            g_cursor[idx]  = run;
            run += c;
        }
    }
    if (t == 1023) g_offsets[NN] = run;
}

__global__ void scatter_kernel(const void* ei) {
    int i = blockIdx.x * blockDim.x + threadIdx.x;
    if (i >= ET) return;
    int is64 = g_is64;
    int src, dst;
    if (i < EE) {
        src = edge_at(ei, i, is64);
        dst = edge_at(ei, (long long)EE + i, is64);
    } else {
        src = i - EE; dst = src;
    }
    int pos = atomicAdd(&g_cursor[dst], 1);
    g_srcs[pos] = src;
}

// ---------------- softmax + aggregate + ELU + fc folding ----------------
// warp per dst node; lane = column (2 cols/lane)
__global__ void aggregate_kernel(const float* __restrict__ bias,
                                 const float* __restrict__ fcw) {
    int n    = (blockIdx.x * blockDim.x + threadIdx.x) >> 5;
    int lane = threadIdx.x & 31;
    if (n >= NN) return;

    int start = g_offsets[n];
    int end   = g_offsets[n + 1];
    float adst = g_adst[n];

    // pass 1: segment max (lane-strided)
    float m = -INFINITY;
    for (int i = start + lane; i < end; i += 32) {
        float e = g_asrc[g_srcs[i]] + adst;
        e = (e > 0.f) ? e : NEG_SLOPE * e;
        m = fmaxf(m, e);
    }
    #pragma unroll
    for (int o = 16; o; o >>= 1) m = fmaxf(m, __shfl_xor_sync(0xffffffffu, m, o));

    // pass 2: exp-weights + message accumulation (edge-sequential, lane=column)
    float acc0 = 0.f, acc1 = 0.f, wsum = 0.f;
    for (int i = start; i < end; i++) {
        int s = g_srcs[i];                       // broadcast load
        float e = g_asrc[s] + adst;
        e = (e > 0.f) ? e : NEG_SLOPE * e;
        float w = __expf(e - m);
        wsum += w;
        const float* hrow = &g_h[(long long)s * HID];
        acc0 = fmaf(w, hrow[lane],      acc0);
        acc1 = fmaf(w, hrow[32 + lane], acc1);
    }
    float inv = 1.0f / wsum;
    float o0 = acc0 * inv + bias[lane];
    float o1 = acc1 * inv + bias[32 + lane];
    o0 = (o0 > 0.f) ? o0 : expm1f(o0);           // ELU
    o1 = (o1 > 0.f) ? o1 : expm1f(o1);

    // fold fc: s0 = h_elu·fc_w[:64], s1 = h_elu·fc_w[64:]
    float p0 = o0 * fcw[lane]      + o1 * fcw[32 + lane];
    float p1 = o0 * fcw[64 + lane] + o1 * fcw[96 + lane];
    #pragma unroll
    for (int o = 16; o; o >>= 1) {
        p0 += __shfl_xor_sync(0xffffffffu, p0, o);
        p1 += __shfl_xor_sync(0xffffffffu, p1, o);
    }
    if (lane == 0) { g_s0[n] = p0; g_s1[n] = p1; }
}

// ---------------- per-edge scores ----------------
__global__ void score_kernel(const void* ei, const float* __restrict__ fcb,
                             float* __restrict__ out) {
    int e = blockIdx.x * blockDim.x + threadIdx.x;
    if (e >= EE) return;
    int is64 = g_is64;
    int s = edge_at(ei, e, is64);
    int d = edge_at(ei, (long long)EE + e, is64);
    out[e] = g_s0[s] + g_s1[d] + fcb[0];
}

// ---------------- launch ----------------
extern "C" void kernel_launch(void* const* d_in, const int* in_sizes, int n_in,
                              void* d_out, int out_size) {
    const float* x   = (const float*)d_in[0];
    const void*  ei  = d_in[1];
    const float* W   = (const float*)d_in[2];
    const float* asv = (const float*)d_in[3];
    const float* adv = (const float*)d_in[4];
    const float* bias= (const float*)d_in[5];
    const float* fcw = (const float*)d_in[6];
    const float* fcb = (const float*)d_in[7];
    float* out = (float*)d_out;

    detect_kernel<<<1, 64>>>((const int*)ei);
    zero_kernel<<<(NN + 255) / 256, 256>>>();
    gemm_kernel<<<(NN + 31) / 32, 128>>>(x, W);
    attn_kernel<<<(NN * 32 + 255) / 256, 256>>>(asv, adv);
    hist_kernel<<<(ET + 255) / 256, 256>>>(ei);
    scan_kernel<<<1, 1024>>>();
    scatter_kernel<<<(ET + 255) / 256, 256>>>(ei);
    aggregate_kernel<<<(NN * 32 + 255) / 256, 256>>>(bias, fcw);
    score_kernel<<<(EE + 255) / 256, 256>>>(ei, fcb, out);
}

// round 3
// speedup vs baseline: 1.0588x; 1.0588x over previous
#include <cuda_runtime.h>
#include <math.h>

#define NN   50000
#define EE   800000
#define ET   (EE + NN)        // edges + self loops
#define FIN  128
#define HID  64
#define NEG_SLOPE 0.2f

// ---------------- scratch (device globals; no allocs allowed) ----------------
__device__ float g_h[NN * HID];        // x @ W
__device__ float g_asrc[NN];
__device__ float g_adst[NN];
__device__ int   g_count[NN];          // degree histogram
__device__ int   g_cursor[NN];         // scatter cursors
__device__ int   g_offsets[NN + 1];    // CSR offsets
__device__ int   g_srcs[ET];           // src node per CSR slot
__device__ int   g_src32[EE];          // int32 copies of edge_index
__device__ int   g_dst32[EE];
__device__ float g_s0[NN];
__device__ float g_s1[NN];
__device__ int   g_is64;

__device__ __forceinline__ int edge_at(const void* p, long long i, int is64) {
    return is64 ? (int)((const long long*)p)[i] : ((const int*)p)[i];
}

// ---------------- init: counts=1 (self-loop pre-counted) + dtype detect ----
__global__ void init_kernel(const int* ew) {
    int i = blockIdx.x * blockDim.x + threadIdx.x;
    if (i < NN) g_count[i] = 1;          // self loop contributes 1 per node
    if (i == 0) {
        int all0 = 1;
        #pragma unroll 8
        for (int j = 0; j < 64; j++) {
            if (ew[2 * j + 1] != 0) { all0 = 0; break; }
        }
        g_is64 = all0;
    }
}

// ---------------- GEMM + attn epilogue ----------------
// 32-row x 64-col tile per block, 128 threads, 4x4 outputs per thread.
// Epilogue reduces per-row dots with att_src/att_dst into g_asrc/g_adst.
__global__ void gemm_kernel(const float* __restrict__ x, const float* __restrict__ W,
                            const float* __restrict__ att_src, const float* __restrict__ att_dst) {
    __shared__ float xsT[FIN][32];   // transposed: [k][row]  16KB
    __shared__ float Ws[FIN][HID];   // [k][col]              32KB

    const int tid  = threadIdx.x;
    const int row0 = blockIdx.x * 32;
    const int tr   = tid >> 4;   // 0..7
    const int tc   = tid & 15;   // 0..15

    #pragma unroll
    for (int it = 0; it < 8; it++) {
        int f  = it * 128 + tid;
        int r  = f >> 5;
        int k4 = f & 31;
        float4 v = make_float4(0.f, 0.f, 0.f, 0.f);
        if (row0 + r < NN)
            v = *(const float4*)&x[(long long)(row0 + r) * FIN + k4 * 4];
        xsT[k4 * 4 + 0][r] = v.x;
        xsT[k4 * 4 + 1][r] = v.y;
        xsT[k4 * 4 + 2][r] = v.z;
        xsT[k4 * 4 + 3][r] = v.w;
    }
    #pragma unroll
    for (int it = 0; it < 16; it++) {
        int f  = it * 128 + tid;
        int kk = f >> 4;
        int c4 = f & 15;
        *(float4*)&Ws[kk][c4 * 4] = *(const float4*)&W[kk * HID + c4 * 4];
    }
    __syncthreads();

    float acc[4][4];
    #pragma unroll
    for (int i = 0; i < 4; i++)
        #pragma unroll
        for (int j = 0; j < 4; j++) acc[i][j] = 0.f;

    #pragma unroll 4
    for (int k = 0; k < FIN; k++) {
        float4 a = *(const float4*)&xsT[k][tr * 4];
        float4 b = *(const float4*)&Ws[k][tc * 4];
        acc[0][0] += a.x * b.x; acc[0][1] += a.x * b.y; acc[0][2] += a.x * b.z; acc[0][3] += a.x * b.w;
        acc[1][0] += a.y * b.x; acc[1][1] += a.y * b.y; acc[1][2] += a.y * b.z; acc[1][3] += a.y * b.w;
        acc[2][0] += a.z * b.x; acc[2][1] += a.z * b.y; acc[2][2] += a.z * b.z; acc[2][3] += a.z * b.w;
        acc[3][0] += a.w * b.x; acc[3][1] += a.w * b.y; acc[3][2] += a.w * b.z; acc[3][3] += a.w * b.w;
    }

    // store h
    #pragma unroll
    for (int i = 0; i < 4; i++) {
        int r = row0 + tr * 4 + i;
        if (r < NN) {
            float4 v = make_float4(acc[i][0], acc[i][1], acc[i][2], acc[i][3]);
            *(float4*)&g_h[(long long)r * HID + tc * 4] = v;
        }
    }

    // attn epilogue: per-row dot with att vectors (reduce over 16 tc threads)
    float as0 = att_src[tc * 4 + 0], as1 = att_src[tc * 4 + 1];
    float as2 = att_src[tc * 4 + 2], as3 = att_src[tc * 4 + 3];
    float ad0 = att_dst[tc * 4 + 0], ad1 = att_dst[tc * 4 + 1];
    float ad2 = att_dst[tc * 4 + 2], ad3 = att_dst[tc * 4 + 3];

    __syncthreads();
    float* redA = (float*)xsT;            // [32][16]
    float* redB = redA + 32 * 16;         // [32][16]
    #pragma unroll
    for (int i = 0; i < 4; i++) {
        int row = tr * 4 + i;
        float pa = acc[i][0] * as0 + acc[i][1] * as1 + acc[i][2] * as2 + acc[i][3] * as3;
        float pb = acc[i][0] * ad0 + acc[i][1] * ad1 + acc[i][2] * ad2 + acc[i][3] * ad3;
        redA[row * 16 + tc] = pa;
        redB[row * 16 + tc] = pb;
    }
    __syncthreads();
    if (tid < 32) {
        int r = row0 + tid;
        if (r < NN) {
            float sa = 0.f, sb = 0.f;
            #pragma unroll
            for (int j = 0; j < 16; j++) { sa += redA[tid * 16 + j]; sb += redB[tid * 16 + j]; }
            g_asrc[r] = sa;
            g_adst[r] = sb;
        }
    }
}

// ---------------- edges: int64->int32 conversion + dst histogram ----------------
__global__ void edges_kernel(const void* ei) {
    int i = blockIdx.x * blockDim.x + threadIdx.x;
    if (i >= EE) return;
    int is64 = g_is64;
    int s = edge_at(ei, i, is64);
    int d = edge_at(ei, (long long)EE + i, is64);
    g_src32[i] = s;
    g_dst32[i] = d;
    atomicAdd(&g_count[d], 1);
}

// ---------------- single-block scan ----------------
__global__ void scan_kernel() {
    __shared__ int sums[1024];
    const int CH = (NN + 1023) / 1024;   // 49
    int t = threadIdx.x;
    int base = t * CH;
    int s = 0;
    for (int j = 0; j < CH; j++) {
        int idx = base + j;
        if (idx < NN) s += g_count[idx];
    }
    sums[t] = s;
    __syncthreads();
    for (int off = 1; off < 1024; off <<= 1) {
        int v = (t >= off) ? sums[t - off] : 0;
        __syncthreads();
        sums[t] += v;
        __syncthreads();
    }
    int run = (t == 0) ? 0 : sums[t - 1];
    for (int j = 0; j < CH; j++) {
        int idx = base + j;
        if (idx < NN) {
            int c = g_count[idx];
            g_offsets[idx] = run;
            g_cursor[idx]  = run;
            run += c;
        }
    }
    if (t == 1023) g_offsets[NN] = run;
}

// ---------------- scatter into CSR ----------------
__global__ void scatter_kernel() {
    int i = blockIdx.x * blockDim.x + threadIdx.x;
    if (i >= ET) return;
    int s, d;
    if (i < EE) { s = g_src32[i]; d = g_dst32[i]; }
    else        { s = d = i - EE; }
    int pos = atomicAdd(&g_cursor[d], 1);
    g_srcs[pos] = s;
}

// ---------------- softmax (max-free) + aggregate + ELU + fc fold ----------------
// warp per dst node; two half-warps process two edges in parallel;
// within a half-warp, 16 lanes x float4 cover the 64-wide h row.
__global__ void aggregate_kernel(const float* __restrict__ bias,
                                 const float* __restrict__ fcw,
                                 const float* __restrict__ fcb) {
    int n    = (blockIdx.x * blockDim.x + threadIdx.x) >> 5;
    int lane = threadIdx.x & 31;
    if (n >= NN) return;
    int sub  = lane >> 4;        // 0/1: which edge of the pair
    int l16  = lane & 15;        // column group

    int start = g_offsets[n];
    int end   = g_offsets[n + 1];
    float adst = g_adst[n];

    float4 acc = make_float4(0.f, 0.f, 0.f, 0.f);
    float wsum = 0.f;
    for (int i = start + sub; i < end; i += 2) {
        int s = g_srcs[i];
        float e = g_asrc[s] + adst;
        e = (e > 0.f) ? e : NEG_SLOPE * e;
        float w = __expf(e);
        wsum += w;
        float4 hv = *(const float4*)&g_h[(long long)s * HID + l16 * 4];
        acc.x = fmaf(w, hv.x, acc.x);
        acc.y = fmaf(w, hv.y, acc.y);
        acc.z = fmaf(w, hv.z, acc.z);
        acc.w = fmaf(w, hv.w, acc.w);
    }
    // combine the two half-warps
    wsum += __shfl_xor_sync(0xffffffffu, wsum, 16);
    acc.x += __shfl_down_sync(0xffffffffu, acc.x, 16);
    acc.y += __shfl_down_sync(0xffffffffu, acc.y, 16);
    acc.z += __shfl_down_sync(0xffffffffu, acc.z, 16);
    acc.w += __shfl_down_sync(0xffffffffu, acc.w, 16);

    float inv = 1.0f / wsum;
    float4 b  = *(const float4*)&bias[l16 * 4];
    float o0 = acc.x * inv + b.x;
    float o1 = acc.y * inv + b.y;
    float o2 = acc.z * inv + b.z;
    float o3 = acc.w * inv + b.w;
    o0 = (o0 > 0.f) ? o0 : expm1f(o0);
    o1 = (o1 > 0.f) ? o1 : expm1f(o1);
    o2 = (o2 > 0.f) ? o2 : expm1f(o2);
    o3 = (o3 > 0.f) ? o3 : expm1f(o3);

    float4 f0 = *(const float4*)&fcw[l16 * 4];
    float4 f1 = *(const float4*)&fcw[HID + l16 * 4];
    float p0 = o0 * f0.x + o1 * f0.y + o2 * f0.z + o3 * f0.w;
    float p1 = o0 * f1.x + o1 * f1.y + o2 * f1.z + o3 * f1.w;
    #pragma unroll
    for (int o = 8; o; o >>= 1) {
        p0 += __shfl_xor_sync(0xffffffffu, p0, o);
        p1 += __shfl_xor_sync(0xffffffffu, p1, o);
    }
    if (lane == 0) {
        g_s0[n] = p0 + fcb[0];   // fold fc bias into s0
        g_s1[n] = p1;
    }
}

// ---------------- per-edge scores (4 edges per thread) ----------------
__global__ void score_kernel(float* __restrict__ out) {
    int t = blockIdx.x * blockDim.x + threadIdx.x;
    int e0 = t * 4;
    if (e0 >= EE) return;
    if (e0 + 4 <= EE) {
        int4 s4 = *(const int4*)&g_src32[e0];
        int4 d4 = *(const int4*)&g_dst32[e0];
        float4 r;
        r.x = g_s0[s4.x] + g_s1[d4.x];
        r.y = g_s0[s4.y] + g_s1[d4.y];
        r.z = g_s0[s4.z] + g_s1[d4.z];
        r.w = g_s0[s4.w] + g_s1[d4.w];
        *(float4*)&out[e0] = r;
    } else {
        for (int e = e0; e < EE; e++)
            out[e] = g_s0[g_src32[e]] + g_s1[g_dst32[e]];
    }
}

// ---------------- launch ----------------
extern "C" void kernel_launch(void* const* d_in, const int* in_sizes, int n_in,
                              void* d_out, int out_size) {
    const float* x   = (const float*)d_in[0];
    const void*  ei  = d_in[1];
    const float* W   = (const float*)d_in[2];
    const float* asv = (const float*)d_in[3];
    const float* adv = (const float*)d_in[4];
    const float* bias= (const float*)d_in[5];
    const float* fcw = (const float*)d_in[6];
    const float* fcb = (const float*)d_in[7];
    float* out = (float*)d_out;

    init_kernel<<<(NN + 255) / 256, 256>>>((const int*)ei);
    gemm_kernel<<<(NN + 31) / 32, 128>>>(x, W, asv, adv);
    edges_kernel<<<(EE + 255) / 256, 256>>>(ei);
    scan_kernel<<<1, 1024>>>();
    scatter_kernel<<<(ET + 255) / 256, 256>>>();
    aggregate_kernel<<<(NN * 32 + 255) / 256, 256>>>(bias, fcw, fcb);
    score_kernel<<<(EE / 4 + 255) / 256, 256>>>(out);
}

// round 5
// speedup vs baseline: 1.6893x; 1.5955x over previous
#include <cuda_runtime.h>
#include <math.h>

#define NN   50000
#define EE   800000
#define ET   (EE + NN)        // edges + self loops
#define FIN  128
#define HID  64
#define NEG_SLOPE 0.2f

#define SCAN_B   256
#define SCAN_G   ((NN + SCAN_B - 1) / SCAN_B)   // 196
#define NWARPS   (SCAN_B / 32)                  // 8

// ---------------- scratch (device globals; no allocs allowed) ----------------
__device__ float g_h[NN * HID];        // x @ W
__device__ float g_asrc[NN];
__device__ float g_adst[NN];
__device__ int   g_count[NN];          // degree histogram
__device__ int   g_cursor[NN];         // scatter cursors
__device__ int   g_offsets[NN + 1];    // CSR offsets
__device__ int   g_srcs[ET];           // src node per CSR slot
__device__ int   g_src32[EE];          // int32 copies of edge_index
__device__ int   g_dst32[EE];
__device__ float g_s0[NN];
__device__ float g_s1[NN];
__device__ int   g_bsum[SCAN_G];       // per-block count sums
__device__ int   g_bpre[SCAN_G];       // exclusive prefix of block sums
__device__ int   g_is64;

__device__ __forceinline__ int edge_at(const void* p, long long i, int is64) {
    return is64 ? (int)((const long long*)p)[i] : ((const int*)p)[i];
}

// ---------------- init: counts=1 (self-loop pre-counted) + dtype detect ----
__global__ void init_kernel(const int* ew) {
    int i = blockIdx.x * blockDim.x + threadIdx.x;
    if (i < NN) g_count[i] = 1;          // self loop contributes 1 per node
    if (i == 0) {
        int all0 = 1;
        #pragma unroll 8
        for (int j = 0; j < 64; j++) {
            if (ew[2 * j + 1] != 0) { all0 = 0; break; }
        }
        g_is64 = all0;
    }
}

// ---------------- GEMM + attn epilogue ----------------
__global__ void gemm_kernel(const float* __restrict__ x, const float* __restrict__ W,
                            const float* __restrict__ att_src, const float* __restrict__ att_dst) {
    __shared__ float xsT[FIN][32];   // transposed: [k][row]  16KB
    __shared__ float Ws[FIN][HID];   // [k][col]              32KB

    const int tid  = threadIdx.x;
    const int row0 = blockIdx.x * 32;
    const int tr   = tid >> 4;   // 0..7
    const int tc   = tid & 15;   // 0..15

    #pragma unroll
    for (int it = 0; it < 8; it++) {
        int f  = it * 128 + tid;
        int r  = f >> 5;
        int k4 = f & 31;
        float4 v = make_float4(0.f, 0.f, 0.f, 0.f);
        if (row0 + r < NN)
            v = *(const float4*)&x[(long long)(row0 + r) * FIN + k4 * 4];
        xsT[k4 * 4 + 0][r] = v.x;
        xsT[k4 * 4 + 1][r] = v.y;
        xsT[k4 * 4 + 2][r] = v.z;
        xsT[k4 * 4 + 3][r] = v.w;
    }
    #pragma unroll
    for (int it = 0; it < 16; it++) {
        int f  = it * 128 + tid;
        int kk = f >> 4;
        int c4 = f & 15;
        *(float4*)&Ws[kk][c4 * 4] = *(const float4*)&W[kk * HID + c4 * 4];
    }
    __syncthreads();

    float acc[4][4];
    #pragma unroll
    for (int i = 0; i < 4; i++)
        #pragma unroll
        for (int j = 0; j < 4; j++) acc[i][j] = 0.f;

    #pragma unroll 4
    for (int k = 0; k < FIN; k++) {
        float4 a = *(const float4*)&xsT[k][tr * 4];
        float4 b = *(const float4*)&Ws[k][tc * 4];
        acc[0][0] += a.x * b.x; acc[0][1] += a.x * b.y; acc[0][2] += a.x * b.z; acc[0][3] += a.x * b.w;
        acc[1][0] += a.y * b.x; acc[1][1] += a.y * b.y; acc[1][2] += a.y * b.z; acc[1][3] += a.y * b.w;
        acc[2][0] += a.z * b.x; acc[2][1] += a.z * b.y; acc[2][2] += a.z * b.z; acc[2][3] += a.z * b.w;
        acc[3][0] += a.w * b.x; acc[3][1] += a.w * b.y; acc[3][2] += a.w * b.z; acc[3][3] += a.w * b.w;
    }

    // store h
    #pragma unroll
    for (int i = 0; i < 4; i++) {
        int r = row0 + tr * 4 + i;
        if (r < NN) {
            float4 v = make_float4(acc[i][0], acc[i][1], acc[i][2], acc[i][3]);
            *(float4*)&g_h[(long long)r * HID + tc * 4] = v;
        }
    }

    // attn epilogue
    float as0 = att_src[tc * 4 + 0], as1 = att_src[tc * 4 + 1];
    float as2 = att_src[tc * 4 + 2], as3 = att_src[tc * 4 + 3];
    float ad0 = att_dst[tc * 4 + 0], ad1 = att_dst[tc * 4 + 1];
    float ad2 = att_dst[tc * 4 + 2], ad3 = att_dst[tc * 4 + 3];

    __syncthreads();
    float* redA = (float*)xsT;            // [32][16]
    float* redB = redA + 32 * 16;         // [32][16]
    #pragma unroll
    for (int i = 0; i < 4; i++) {
        int row = tr * 4 + i;
        float pa = acc[i][0] * as0 + acc[i][1] * as1 + acc[i][2] * as2 + acc[i][3] * as3;
        float pb = acc[i][0] * ad0 + acc[i][1] * ad1 + acc[i][2] * ad2 + acc[i][3] * ad3;
        redA[row * 16 + tc] = pa;
        redB[row * 16 + tc] = pb;
    }
    __syncthreads();
    if (tid < 32) {
        int r = row0 + tid;
        if (r < NN) {
            float sa = 0.f, sb = 0.f;
            #pragma unroll
            for (int j = 0; j < 16; j++) { sa += redA[tid * 16 + j]; sb += redB[tid * 16 + j]; }
            g_asrc[r] = sa;
            g_adst[r] = sb;
        }
    }
}

// ---------------- edges: int64->int32 conversion + dst histogram ----------------
__global__ void edges_kernel(const void* ei) {
    int i = blockIdx.x * blockDim.x + threadIdx.x;
    if (i >= EE) return;
    int is64 = g_is64;
    int s = edge_at(ei, i, is64);
    int d = edge_at(ei, (long long)EE + i, is64);
    g_src32[i] = s;
    g_dst32[i] = d;
    atomicAdd(&g_count[d], 1);
}

// ---------------- multi-block scan: phase 1 (block sums) ----------------
__global__ void scan1_kernel() {
    __shared__ int wsum[NWARPS];
    int i = blockIdx.x * SCAN_B + threadIdx.x;
    int lane = threadIdx.x & 31;
    int warp = threadIdx.x >> 5;
    int c = (i < NN) ? g_count[i] : 0;
    int v = c;
    #pragma unroll
    for (int o = 16; o; o >>= 1) v += __shfl_xor_sync(0xffffffffu, v, o);
    if (lane == 0) wsum[warp] = v;
    __syncthreads();
    if (threadIdx.x == 0) {
        int s = 0;
        #pragma unroll
        for (int w = 0; w < NWARPS; w++) s += wsum[w];
        g_bsum[blockIdx.x] = s;
    }
}

// ---------------- phase 2: scan block sums (single small block) ----------------
__global__ void scan2_kernel() {
    __shared__ int sh[SCAN_B];
    int t = threadIdx.x;
    int v = (t < SCAN_G) ? g_bsum[t] : 0;
    sh[t] = v;
    __syncthreads();
    // inclusive scan over 256 elements (all threads execute every iteration)
    for (int off = 1; off < SCAN_B; off <<= 1) {
        int add = (t >= off) ? sh[t - off] : 0;
        __syncthreads();
        sh[t] += add;
        __syncthreads();
    }
    if (t < SCAN_G) g_bpre[t] = sh[t] - v;       // exclusive prefix
    if (t == SCAN_B - 1) g_offsets[NN] = sh[t];  // total = ET
}

// ---------------- phase 3: downsweep (per-block exclusive scan + prefix) ----
__global__ void scan3_kernel() {
    __shared__ int wpre[NWARPS];
    int i = blockIdx.x * SCAN_B + threadIdx.x;
    int lane = threadIdx.x & 31;
    int warp = threadIdx.x >> 5;
    int c = (i < NN) ? g_count[i] : 0;
    // warp inclusive scan (full warp active)
    int v = c;
    #pragma unroll
    for (int o = 1; o < 32; o <<= 1) {
        int u = __shfl_up_sync(0xffffffffu, v, o);
        if (lane >= o) v += u;
    }
    if (lane == 31) wpre[warp] = v;
    __syncthreads();
    // cross-warp scan: ALL 32 lanes of warp 0 run the shuffles (mask must match)
    if (warp == 0) {
        int u = (lane < NWARPS) ? wpre[lane] : 0;
        int s = u;
        #pragma unroll
        for (int o = 1; o < 32; o <<= 1) {
            int t2 = __shfl_up_sync(0xffffffffu, s, o);
            if (lane >= o) s += t2;
        }
        if (lane < NWARPS) wpre[lane] = s - u;   // exclusive across warps
    }
    __syncthreads();
    if (i < NN) {
        int off = g_bpre[blockIdx.x] + wpre[warp] + (v - c);  // exclusive
        g_offsets[i] = off;
        g_cursor[i]  = off;
    }
}

// ---------------- scatter into CSR ----------------
__global__ void scatter_kernel() {
    int i = blockIdx.x * blockDim.x + threadIdx.x;
    if (i >= ET) return;
    int s, d;
    if (i < EE) { s = g_src32[i]; d = g_dst32[i]; }
    else        { s = d = i - EE; }
    int pos = atomicAdd(&g_cursor[d], 1);
    g_srcs[pos] = s;
}

// ---------------- softmax (max-free) + aggregate + ELU + fc fold ----------------
__global__ void aggregate_kernel(const float* __restrict__ bias,
                                 const float* __restrict__ fcw,
                                 const float* __restrict__ fcb) {
    int n    = (blockIdx.x * blockDim.x + threadIdx.x) >> 5;
    int lane = threadIdx.x & 31;
    if (n >= NN) return;
    int sub  = lane >> 4;        // 0/1: which edge of the pair
    int l16  = lane & 15;        // column group

    int start = g_offsets[n];
    int end   = g_offsets[n + 1];
    float adst = g_adst[n];

    float4 acc = make_float4(0.f, 0.f, 0.f, 0.f);
    float wsum = 0.f;
    for (int i = start + sub; i < end; i += 2) {
        int s = g_srcs[i];
        float e = g_asrc[s] + adst;
        e = (e > 0.f) ? e : NEG_SLOPE * e;
        float w = __expf(e);
        wsum += w;
        float4 hv = *(const float4*)&g_h[(long long)s * HID + l16 * 4];
        acc.x = fmaf(w, hv.x, acc.x);
        acc.y = fmaf(w, hv.y, acc.y);
        acc.z = fmaf(w, hv.z, acc.z);
        acc.w = fmaf(w, hv.w, acc.w);
    }
    wsum += __shfl_xor_sync(0xffffffffu, wsum, 16);
    acc.x += __shfl_down_sync(0xffffffffu, acc.x, 16);
    acc.y += __shfl_down_sync(0xffffffffu, acc.y, 16);
    acc.z += __shfl_down_sync(0xffffffffu, acc.z, 16);
    acc.w += __shfl_down_sync(0xffffffffu, acc.w, 16);

    float inv = 1.0f / wsum;
    float4 b  = *(const float4*)&bias[l16 * 4];
    float o0 = acc.x * inv + b.x;
    float o1 = acc.y * inv + b.y;
    float o2 = acc.z * inv + b.z;
    float o3 = acc.w * inv + b.w;
    o0 = (o0 > 0.f) ? o0 : expm1f(o0);
    o1 = (o1 > 0.f) ? o1 : expm1f(o1);
    o2 = (o2 > 0.f) ? o2 : expm1f(o2);
    o3 = (o3 > 0.f) ? o3 : expm1f(o3);

    float4 f0 = *(const float4*)&fcw[l16 * 4];
    float4 f1 = *(const float4*)&fcw[HID + l16 * 4];
    float p0 = o0 * f0.x + o1 * f0.y + o2 * f0.z + o3 * f0.w;
    float p1 = o0 * f1.x + o1 * f1.y + o2 * f1.z + o3 * f1.w;
    #pragma unroll
    for (int o = 8; o; o >>= 1) {
        p0 += __shfl_xor_sync(0xffffffffu, p0, o);
        p1 += __shfl_xor_sync(0xffffffffu, p1, o);
    }
    if (lane == 0) {
        g_s0[n] = p0 + fcb[0];   // fold fc bias into s0
        g_s1[n] = p1;
    }
}

// ---------------- per-edge scores (4 edges per thread) ----------------
__global__ void score_kernel(float* __restrict__ out) {
    int t = blockIdx.x * blockDim.x + threadIdx.x;
    int e0 = t * 4;
    if (e0 >= EE) return;
    if (e0 + 4 <= EE) {
        int4 s4 = *(const int4*)&g_src32[e0];
        int4 d4 = *(const int4*)&g_dst32[e0];
        float4 r;
        r.x = g_s0[s4.x] + g_s1[d4.x];
        r.y = g_s0[s4.y] + g_s1[d4.y];
        r.z = g_s0[s4.z] + g_s1[d4.z];
        r.w = g_s0[s4.w] + g_s1[d4.w];
        *(float4*)&out[e0] = r;
    } else {
        for (int e = e0; e < EE; e++)
            out[e] = g_s0[g_src32[e]] + g_s1[g_dst32[e]];
    }
}

// ---------------- launch ----------------
extern "C" void kernel_launch(void* const* d_in, const int* in_sizes, int n_in,
                              void* d_out, int out_size) {
    const float* x   = (const float*)d_in[0];
    const void*  ei  = d_in[1];
    const float* W   = (const float*)d_in[2];
    const float* asv = (const float*)d_in[3];
    const float* adv = (const float*)d_in[4];
    const float* bias= (const float*)d_in[5];
    const float* fcw = (const float*)d_in[6];
    const float* fcb = (const float*)d_in[7];
    float* out = (float*)d_out;

    init_kernel<<<(NN + 255) / 256, 256>>>((const int*)ei);
    gemm_kernel<<<(NN + 31) / 32, 128>>>(x, W, asv, adv);
    edges_kernel<<<(EE + 255) / 256, 256>>>(ei);
    scan1_kernel<<<SCAN_G, SCAN_B>>>();
    scan2_kernel<<<1, SCAN_B>>>();
    scan3_kernel<<<SCAN_G, SCAN_B>>>();
    scatter_kernel<<<(ET + 255) / 256, 256>>>();
    aggregate_kernel<<<(NN * 32 + 255) / 256, 256>>>(bias, fcw, fcb);
    score_kernel<<<(EE / 4 + 255) / 256, 256>>>(out);
}

// round 6
// speedup vs baseline: 2.0603x; 1.2196x over previous
#include <cuda_runtime.h>
#include <math.h>

#define NN   50000
#define EE   800000
#define ET   (EE + NN)        // edges + self loops
#define FIN  128
#define HID  64
#define NEG_SLOPE 0.2f

#define SCAN_B   256
#define SCAN_G   ((NN + SCAN_B - 1) / SCAN_B)   // 196
#define NWARPS   (SCAN_B / 32)                  // 8

#define GR   128              // gemm rows per block
#define KCH  32               // gemm k-chunk per phase
#define XPAD 4                // row padding for transpose store

// ---------------- scratch (device globals; no allocs allowed) ----------------
__device__ float g_h[NN * HID];        // x @ W
__device__ float g_asrc[NN];
__device__ float g_adst[NN];
__device__ int   g_count[NN];          // degree histogram
__device__ int   g_cursor[NN];         // scatter cursors
__device__ int   g_offsets[NN + 1];    // CSR offsets
__device__ int   g_srcs[ET];           // src node per CSR slot
__device__ float g_wts[ET];            // precomputed exp(leaky(e)) per CSR slot
__device__ int   g_src32[EE];          // int32 copies of edge_index
__device__ int   g_dst32[EE];
__device__ float g_s0[NN];
__device__ float g_s1[NN];
__device__ int   g_bsum[SCAN_G];       // per-block count sums
__device__ int   g_bpre[SCAN_G];       // exclusive prefix of block sums
__device__ int   g_is64;

__device__ __forceinline__ int edge_at(const void* p, long long i, int is64) {
    return is64 ? (int)((const long long*)p)[i] : ((const int*)p)[i];
}

// packed fp32x2 helpers (Blackwell)
__device__ __forceinline__ unsigned long long fma2(unsigned long long a,
                                                   unsigned long long b,
                                                   unsigned long long c) {
    unsigned long long d;
    asm("fma.rn.f32x2 %0, %1, %2, %3;" : "=l"(d) : "l"(a), "l"(b), "l"(c));
    return d;
}
__device__ __forceinline__ unsigned long long pack2(float lo, float hi) {
    unsigned long long r;
    asm("mov.b64 %0, {%1, %2};" : "=l"(r) : "f"(lo), "f"(hi));
    return r;
}
__device__ __forceinline__ float2 unpack2(unsigned long long v) {
    float2 r;
    asm("mov.b64 {%0, %1}, %2;" : "=f"(r.x), "=f"(r.y) : "l"(v));
    return r;
}

// ---------------- init: counts=1 (self-loop pre-counted) + dtype detect ----
__global__ void init_kernel(const int* ew) {
    int i = blockIdx.x * blockDim.x + threadIdx.x;
    if (i < NN) g_count[i] = 1;          // self loop contributes 1 per node
    if (i == 0) {
        int all0 = 1;
        #pragma unroll 8
        for (int j = 0; j < 64; j++) {
            if (ew[2 * j + 1] != 0) { all0 = 0; break; }
        }
        g_is64 = all0;
    }
}

// ---------------- GEMM (f32x2) + attn epilogue ----------------
// 128-row x 64-col tile per block, 128 threads, 8x8 per thread,
// k processed in 4 phases of 32.
__global__ void gemm_kernel(const float* __restrict__ x, const float* __restrict__ W,
                            const float* __restrict__ att_src, const float* __restrict__ att_dst) {
    __shared__ float xsT[KCH][GR + XPAD];   // [k][row]  ~16.5KB
    __shared__ float Ws[KCH][HID];          // [k][col]   8KB

    const int tid  = threadIdx.x;
    const int row0 = blockIdx.x * GR;
    const int tr   = tid >> 3;   // 0..15  (rows tr*8 .. tr*8+7)
    const int tc   = tid & 7;    // 0..7   (cols tc*8 .. tc*8+7)

    unsigned long long acc[8][4];
    #pragma unroll
    for (int i = 0; i < 8; i++)
        #pragma unroll
        for (int j = 0; j < 4; j++) acc[i][j] = 0ull;

    #pragma unroll
    for (int ph = 0; ph < FIN / KCH; ph++) {
        // load x slice: 128 rows x 32 k = 1024 float4, 8 per thread (transposed store)
        #pragma unroll
        for (int it = 0; it < 8; it++) {
            int f  = it * 128 + tid;       // 0..1023
            int r  = f >> 3;               // 0..127
            int k4 = f & 7;                // 0..7
            float4 v = make_float4(0.f, 0.f, 0.f, 0.f);
            if (row0 + r < NN)
                v = *(const float4*)&x[(long long)(row0 + r) * FIN + ph * KCH + k4 * 4];
            xsT[k4 * 4 + 0][r] = v.x;
            xsT[k4 * 4 + 1][r] = v.y;
            xsT[k4 * 4 + 2][r] = v.z;
            xsT[k4 * 4 + 3][r] = v.w;
        }
        // load W slice: 32 k x 64 cols = 512 float4, 4 per thread
        #pragma unroll
        for (int it = 0; it < 4; it++) {
            int f  = it * 128 + tid;       // 0..511
            int kk = f >> 4;               // 0..31
            int c4 = f & 15;               // 0..15
            *(float4*)&Ws[kk][c4 * 4] = *(const float4*)&W[(ph * KCH + kk) * HID + c4 * 4];
        }
        __syncthreads();

        #pragma unroll 4
        for (int k = 0; k < KCH; k++) {
            float4 a0 = *(const float4*)&xsT[k][tr * 8];
            float4 a1 = *(const float4*)&xsT[k][tr * 8 + 4];
            const unsigned long long* bp = (const unsigned long long*)&Ws[k][tc * 8];
            unsigned long long b0 = bp[0], b1 = bp[1], b2 = bp[2], b3 = bp[3];
            float a[8] = {a0.x, a0.y, a0.z, a0.w, a1.x, a1.y, a1.z, a1.w};
            #pragma unroll
            for (int i = 0; i < 8; i++) {
                unsigned long long ai = pack2(a[i], a[i]);
                acc[i][0] = fma2(ai, b0, acc[i][0]);
                acc[i][1] = fma2(ai, b1, acc[i][1]);
                acc[i][2] = fma2(ai, b2, acc[i][2]);
                acc[i][3] = fma2(ai, b3, acc[i][3]);
            }
        }
        __syncthreads();
    }

    // unpack + store h, and per-row attention partials
    float as[8], ad[8];
    #pragma unroll
    for (int j = 0; j < 8; j++) { as[j] = att_src[tc * 8 + j]; ad[j] = att_dst[tc * 8 + j]; }

    float* redA = (float*)xsT;           // [128][8]
    float* redB = redA + GR * 8;         // [128][8]

    #pragma unroll
    for (int i = 0; i < 8; i++) {
        int row = tr * 8 + i;
        int r   = row0 + row;
        float2 c0 = unpack2(acc[i][0]);
        float2 c1 = unpack2(acc[i][1]);
        float2 c2 = unpack2(acc[i][2]);
        float2 c3 = unpack2(acc[i][3]);
        if (r < NN) {
            float4 v0 = make_float4(c0.x, c0.y, c1.x, c1.y);
            float4 v1 = make_float4(c2.x, c2.y, c3.x, c3.y);
            *(float4*)&g_h[(long long)r * HID + tc * 8]     = v0;
            *(float4*)&g_h[(long long)r * HID + tc * 8 + 4] = v1;
        }
        float pa = c0.x * as[0] + c0.y * as[1] + c1.x * as[2] + c1.y * as[3]
                 + c2.x * as[4] + c2.y * as[5] + c3.x * as[6] + c3.y * as[7];
        float pb = c0.x * ad[0] + c0.y * ad[1] + c1.x * ad[2] + c1.y * ad[3]
                 + c2.x * ad[4] + c2.y * ad[5] + c3.x * ad[6] + c3.y * ad[7];
        redA[row * 8 + tc] = pa;
        redB[row * 8 + tc] = pb;
    }
    __syncthreads();
    {
        int r = row0 + tid;               // tid = row 0..127
        if (r < NN) {
            float sa = 0.f, sb = 0.f;
            #pragma unroll
            for (int j = 0; j < 8; j++) { sa += redA[tid * 8 + j]; sb += redB[tid * 8 + j]; }
            g_asrc[r] = sa;
            g_adst[r] = sb;
        }
    }
}

// ---------------- edges: int64->int32 conversion + dst histogram ----------------
__global__ void edges_kernel(const void* ei) {
    int i = blockIdx.x * blockDim.x + threadIdx.x;
    if (i >= EE) return;
    int is64 = g_is64;
    int s = edge_at(ei, i, is64);
    int d = edge_at(ei, (long long)EE + i, is64);
    g_src32[i] = s;
    g_dst32[i] = d;
    atomicAdd(&g_count[d], 1);
}

// ---------------- multi-block scan: phase 1 (block sums) ----------------
__global__ void scan1_kernel() {
    __shared__ int wsum[NWARPS];
    int i = blockIdx.x * SCAN_B + threadIdx.x;
    int lane = threadIdx.x & 31;
    int warp = threadIdx.x >> 5;
    int c = (i < NN) ? g_count[i] : 0;
    int v = c;
    #pragma unroll
    for (int o = 16; o; o >>= 1) v += __shfl_xor_sync(0xffffffffu, v, o);
    if (lane == 0) wsum[warp] = v;
    __syncthreads();
    if (threadIdx.x == 0) {
        int s = 0;
        #pragma unroll
        for (int w = 0; w < NWARPS; w++) s += wsum[w];
        g_bsum[blockIdx.x] = s;
    }
}

// ---------------- phase 2: scan block sums (single small block) ----------------
__global__ void scan2_kernel() {
    __shared__ int sh[SCAN_B];
    int t = threadIdx.x;
    int v = (t < SCAN_G) ? g_bsum[t] : 0;
    sh[t] = v;
    __syncthreads();
    for (int off = 1; off < SCAN_B; off <<= 1) {
        int add = (t >= off) ? sh[t - off] : 0;
        __syncthreads();
        sh[t] += add;
        __syncthreads();
    }
    if (t < SCAN_G) g_bpre[t] = sh[t] - v;       // exclusive prefix
    if (t == SCAN_B - 1) g_offsets[NN] = sh[t];  // total = ET
}

// ---------------- phase 3: downsweep (per-block exclusive scan + prefix) ----
__global__ void scan3_kernel() {
    __shared__ int wpre[NWARPS];
    int i = blockIdx.x * SCAN_B + threadIdx.x;
    int lane = threadIdx.x & 31;
    int warp = threadIdx.x >> 5;
    int c = (i < NN) ? g_count[i] : 0;
    int v = c;
    #pragma unroll
    for (int o = 1; o < 32; o <<= 1) {
        int u = __shfl_up_sync(0xffffffffu, v, o);
        if (lane >= o) v += u;
    }
    if (lane == 31) wpre[warp] = v;
    __syncthreads();
    if (warp == 0) {
        int u = (lane < NWARPS) ? wpre[lane] : 0;
        int s = u;
        #pragma unroll
        for (int o = 1; o < 32; o <<= 1) {
            int t2 = __shfl_up_sync(0xffffffffu, s, o);
            if (lane >= o) s += t2;
        }
        if (lane < NWARPS) wpre[lane] = s - u;   // exclusive across warps
    }
    __syncthreads();
    if (i < NN) {
        int off = g_bpre[blockIdx.x] + wpre[warp] + (v - c);  // exclusive
        g_offsets[i] = off;
        g_cursor[i]  = off;
    }
}

// ---------------- scatter into CSR + precompute edge weights ----------------
__global__ void scatter_kernel() {
    int i = blockIdx.x * blockDim.x + threadIdx.x;
    if (i >= ET) return;
    int s, d;
    if (i < EE) { s = g_src32[i]; d = g_dst32[i]; }
    else        { s = d = i - EE; }
    int pos = atomicAdd(&g_cursor[d], 1);
    g_srcs[pos] = s;
    float e = g_asrc[s] + g_adst[d];
    e = (e > 0.f) ? e : NEG_SLOPE * e;
    g_wts[pos] = __expf(e);
}

// ---------------- aggregate (precomputed weights) + ELU + fc fold ----------------
// warp per dst node; two half-warps, each unrolled x2 -> 4 edges in flight.
__global__ void aggregate_kernel(const float* __restrict__ bias,
                                 const float* __restrict__ fcw,
                                 const float* __restrict__ fcb) {
    int n    = (blockIdx.x * blockDim.x + threadIdx.x) >> 5;
    int lane = threadIdx.x & 31;
    if (n >= NN) return;
    int sub  = lane >> 4;        // 0/1: parity class of edges
    int l16  = lane & 15;        // column group

    int start = g_offsets[n];
    int end   = g_offsets[n + 1];

    float4 acc = make_float4(0.f, 0.f, 0.f, 0.f);
    float wsum = 0.f;
    int i = start + sub;
    for (; i + 2 < end; i += 4) {
        int   s0 = g_srcs[i];
        int   s1 = g_srcs[i + 2];
        float w0 = g_wts[i];
        float w1 = g_wts[i + 2];
        float4 h0 = *(const float4*)&g_h[(long long)s0 * HID + l16 * 4];
        float4 h1 = *(const float4*)&g_h[(long long)s1 * HID + l16 * 4];
        wsum += w0 + w1;
        acc.x = fmaf(w0, h0.x, fmaf(w1, h1.x, acc.x));
        acc.y = fmaf(w0, h0.y, fmaf(w1, h1.y, acc.y));
        acc.z = fmaf(w0, h0.z, fmaf(w1, h1.z, acc.z));
        acc.w = fmaf(w0, h0.w, fmaf(w1, h1.w, acc.w));
    }
    if (i < end) {
        int   s0 = g_srcs[i];
        float w0 = g_wts[i];
        float4 h0 = *(const float4*)&g_h[(long long)s0 * HID + l16 * 4];
        wsum += w0;
        acc.x = fmaf(w0, h0.x, acc.x);
        acc.y = fmaf(w0, h0.y, acc.y);
        acc.z = fmaf(w0, h0.z, acc.z);
        acc.w = fmaf(w0, h0.w, acc.w);
    }
    wsum += __shfl_xor_sync(0xffffffffu, wsum, 16);
    acc.x += __shfl_down_sync(0xffffffffu, acc.x, 16);
    acc.y += __shfl_down_sync(0xffffffffu, acc.y, 16);
    acc.z += __shfl_down_sync(0xffffffffu, acc.z, 16);
    acc.w += __shfl_down_sync(0xffffffffu, acc.w, 16);

    float inv = 1.0f / wsum;
    float4 b  = *(const float4*)&bias[l16 * 4];
    float o0 = acc.x * inv + b.x;
    float o1 = acc.y * inv + b.y;
    float o2 = acc.z * inv + b.z;
    float o3 = acc.w * inv + b.w;
    o0 = (o0 > 0.f) ? o0 : expm1f(o0);
    o1 = (o1 > 0.f) ? o1 : expm1f(o1);
    o2 = (o2 > 0.f) ? o2 : expm1f(o2);
    o3 = (o3 > 0.f) ? o3 : expm1f(o3);

    float4 f0 = *(const float4*)&fcw[l16 * 4];
    float4 f1 = *(const float4*)&fcw[HID + l16 * 4];
    float p0 = o0 * f0.x + o1 * f0.y + o2 * f0.z + o3 * f0.w;
    float p1 = o0 * f1.x + o1 * f1.y + o2 * f1.z + o3 * f1.w;
    #pragma unroll
    for (int o = 8; o; o >>= 1) {
        p0 += __shfl_xor_sync(0xffffffffu, p0, o);
        p1 += __shfl_xor_sync(0xffffffffu, p1, o);
    }
    if (lane == 0) {
        g_s0[n] = p0 + fcb[0];   // fold fc bias into s0
        g_s1[n] = p1;
    }
}

// ---------------- per-edge scores (4 edges per thread) ----------------
__global__ void score_kernel(float* __restrict__ out) {
    int t = blockIdx.x * blockDim.x + threadIdx.x;
    int e0 = t * 4;
    if (e0 >= EE) return;
    if (e0 + 4 <= EE) {
        int4 s4 = *(const int4*)&g_src32[e0];
        int4 d4 = *(const int4*)&g_dst32[e0];
        float4 r;
        r.x = g_s0[s4.x] + g_s1[d4.x];
        r.y = g_s0[s4.y] + g_s1[d4.y];
        r.z = g_s0[s4.z] + g_s1[d4.z];
        r.w = g_s0[s4.w] + g_s1[d4.w];
        *(float4*)&out[e0] = r;
    } else {
        for (int e = e0; e < EE; e++)
            out[e] = g_s0[g_src32[e]] + g_s1[g_dst32[e]];
    }
}

// ---------------- launch ----------------
extern "C" void kernel_launch(void* const* d_in, const int* in_sizes, int n_in,
                              void* d_out, int out_size) {
    const float* x   = (const float*)d_in[0];
    const void*  ei  = d_in[1];
    const float* W   = (const float*)d_in[2];
    const float* asv = (const float*)d_in[3];
    const float* adv = (const float*)d_in[4];
    const float* bias= (const float*)d_in[5];
    const float* fcw = (const float*)d_in[6];
    const float* fcb = (const float*)d_in[7];
    float* out = (float*)d_out;

    init_kernel<<<(NN + 255) / 256, 256>>>((const int*)ei);
    gemm_kernel<<<(NN + GR - 1) / GR, 128>>>(x, W, asv, adv);
    edges_kernel<<<(EE + 255) / 256, 256>>>(ei);
    scan1_kernel<<<SCAN_G, SCAN_B>>>();
    scan2_kernel<<<1, SCAN_B>>>();
    scan3_kernel<<<SCAN_G, SCAN_B>>>();
    scatter_kernel<<<(ET + 255) / 256, 256>>>();
    aggregate_kernel<<<(NN * 32 + 255) / 256, 256>>>(bias, fcw, fcb);
    score_kernel<<<(EE / 4 + 255) / 256, 256>>>(out);
}

// round 7
// speedup vs baseline: 2.1461x; 1.0417x over previous
#include <cuda_runtime.h>
#include <math.h>

#define NN   50000
#define EE   800000
#define ET   (EE + NN)        // edges + self loops
#define FIN  128
#define HID  64
#define NEG_SLOPE 0.2f

#define SCAN_B   256
#define SCAN_G   ((NN + SCAN_B - 1) / SCAN_B)   // 196
#define NWARPS   (SCAN_B / 32)                  // 8

#define GR   128              // gemm rows per block
#define KCH  32               // gemm k-chunk per phase
#define XPAD 4                // row padding for transpose store

struct __align__(8) EW { int s; float w; };

// ---------------- scratch (device globals; no allocs allowed) ----------------
__device__ float g_h[NN * HID];        // x @ W
__device__ float g_asrc[NN];
__device__ float g_adst[NN];
__device__ int   g_count[NN];          // degree histogram
__device__ int   g_cursor[NN];         // scatter cursors
__device__ int   g_offsets[NN + 1];    // CSR offsets
__device__ EW    g_ew[ET];             // (src, weight) per CSR slot
__device__ int2  g_sd[EE];             // packed (src,dst) int32
__device__ float g_s0[NN];
__device__ float g_s1[NN];
__device__ int   g_bsum[SCAN_G];       // per-block count sums
__device__ int   g_is64;

__device__ __forceinline__ int edge_at(const void* p, long long i, int is64) {
    return is64 ? (int)((const long long*)p)[i] : ((const int*)p)[i];
}

// packed fp32x2 helpers (Blackwell)
__device__ __forceinline__ unsigned long long fma2(unsigned long long a,
                                                   unsigned long long b,
                                                   unsigned long long c) {
    unsigned long long d;
    asm("fma.rn.f32x2 %0, %1, %2, %3;" : "=l"(d) : "l"(a), "l"(b), "l"(c));
    return d;
}
__device__ __forceinline__ unsigned long long pack2(float lo, float hi) {
    unsigned long long r;
    asm("mov.b64 %0, {%1, %2};" : "=l"(r) : "f"(lo), "f"(hi));
    return r;
}
__device__ __forceinline__ float2 unpack2(unsigned long long v) {
    float2 r;
    asm("mov.b64 {%0, %1}, %2;" : "=f"(r.x), "=f"(r.y) : "l"(v));
    return r;
}

// ---------------- init: counts=1 (self-loop pre-counted) + dtype detect ----
__global__ void init_kernel(const int* ew) {
    int i = blockIdx.x * blockDim.x + threadIdx.x;
    if (i < NN) g_count[i] = 1;          // self loop contributes 1 per node
    if (i == 0) {
        int all0 = 1;
        #pragma unroll 8
        for (int j = 0; j < 64; j++) {
            if (ew[2 * j + 1] != 0) { all0 = 0; break; }
        }
        g_is64 = all0;
    }
}

// ---------------- GEMM (f32x2) + attn epilogue ----------------
__global__ void gemm_kernel(const float* __restrict__ x, const float* __restrict__ W,
                            const float* __restrict__ att_src, const float* __restrict__ att_dst) {
    __shared__ float xsT[KCH][GR + XPAD];   // [k][row]  ~16.5KB
    __shared__ float Ws[KCH][HID];          // [k][col]   8KB

    const int tid  = threadIdx.x;
    const int row0 = blockIdx.x * GR;
    const int tr   = tid >> 3;   // 0..15
    const int tc   = tid & 7;    // 0..7

    unsigned long long acc[8][4];
    #pragma unroll
    for (int i = 0; i < 8; i++)
        #pragma unroll
        for (int j = 0; j < 4; j++) acc[i][j] = 0ull;

    #pragma unroll
    for (int ph = 0; ph < FIN / KCH; ph++) {
        #pragma unroll
        for (int it = 0; it < 8; it++) {
            int f  = it * 128 + tid;
            int r  = f >> 3;
            int k4 = f & 7;
            float4 v = make_float4(0.f, 0.f, 0.f, 0.f);
            if (row0 + r < NN)
                v = *(const float4*)&x[(long long)(row0 + r) * FIN + ph * KCH + k4 * 4];
            xsT[k4 * 4 + 0][r] = v.x;
            xsT[k4 * 4 + 1][r] = v.y;
            xsT[k4 * 4 + 2][r] = v.z;
            xsT[k4 * 4 + 3][r] = v.w;
        }
        #pragma unroll
        for (int it = 0; it < 4; it++) {
            int f  = it * 128 + tid;
            int kk = f >> 4;
            int c4 = f & 15;
            *(float4*)&Ws[kk][c4 * 4] = *(const float4*)&W[(ph * KCH + kk) * HID + c4 * 4];
        }
        __syncthreads();

        #pragma unroll 4
        for (int k = 0; k < KCH; k++) {
            float4 a0 = *(const float4*)&xsT[k][tr * 8];
            float4 a1 = *(const float4*)&xsT[k][tr * 8 + 4];
            const unsigned long long* bp = (const unsigned long long*)&Ws[k][tc * 8];
            unsigned long long b0 = bp[0], b1 = bp[1], b2 = bp[2], b3 = bp[3];
            float a[8] = {a0.x, a0.y, a0.z, a0.w, a1.x, a1.y, a1.z, a1.w};
            #pragma unroll
            for (int i = 0; i < 8; i++) {
                unsigned long long ai = pack2(a[i], a[i]);
                acc[i][0] = fma2(ai, b0, acc[i][0]);
                acc[i][1] = fma2(ai, b1, acc[i][1]);
                acc[i][2] = fma2(ai, b2, acc[i][2]);
                acc[i][3] = fma2(ai, b3, acc[i][3]);
            }
        }
        __syncthreads();
    }

    float as[8], ad[8];
    #pragma unroll
    for (int j = 0; j < 8; j++) { as[j] = att_src[tc * 8 + j]; ad[j] = att_dst[tc * 8 + j]; }

    float* redA = (float*)xsT;           // [128][8]
    float* redB = redA + GR * 8;         // [128][8]

    #pragma unroll
    for (int i = 0; i < 8; i++) {
        int row = tr * 8 + i;
        int r   = row0 + row;
        float2 c0 = unpack2(acc[i][0]);
        float2 c1 = unpack2(acc[i][1]);
        float2 c2 = unpack2(acc[i][2]);
        float2 c3 = unpack2(acc[i][3]);
        if (r < NN) {
            float4 v0 = make_float4(c0.x, c0.y, c1.x, c1.y);
            float4 v1 = make_float4(c2.x, c2.y, c3.x, c3.y);
            *(float4*)&g_h[(long long)r * HID + tc * 8]     = v0;
            *(float4*)&g_h[(long long)r * HID + tc * 8 + 4] = v1;
        }
        float pa = c0.x * as[0] + c0.y * as[1] + c1.x * as[2] + c1.y * as[3]
                 + c2.x * as[4] + c2.y * as[5] + c3.x * as[6] + c3.y * as[7];
        float pb = c0.x * ad[0] + c0.y * ad[1] + c1.x * ad[2] + c1.y * ad[3]
                 + c2.x * ad[4] + c2.y * ad[5] + c3.x * ad[6] + c3.y * ad[7];
        redA[row * 8 + tc] = pa;
        redB[row * 8 + tc] = pb;
    }
    __syncthreads();
    {
        int r = row0 + tid;
        if (r < NN) {
            float sa = 0.f, sb = 0.f;
            #pragma unroll
            for (int j = 0; j < 8; j++) { sa += redA[tid * 8 + j]; sb += redB[tid * 8 + j]; }
            g_asrc[r] = sa;
            g_adst[r] = sb;
        }
    }
}

// ---------------- edges: int64->int32 packed conversion + dst histogram ----------------
__global__ void edges_kernel(const void* ei) {
    int i = blockIdx.x * blockDim.x + threadIdx.x;
    if (i >= EE) return;
    int is64 = g_is64;
    int s = edge_at(ei, i, is64);
    int d = edge_at(ei, (long long)EE + i, is64);
    g_sd[i] = make_int2(s, d);
    atomicAdd(&g_count[d], 1);
}

// ---------------- scan phase 1 (block sums) ----------------
__global__ void scan1_kernel() {
    __shared__ int wsum[NWARPS];
    int i = blockIdx.x * SCAN_B + threadIdx.x;
    int lane = threadIdx.x & 31;
    int warp = threadIdx.x >> 5;
    int c = (i < NN) ? g_count[i] : 0;
    int v = c;
    #pragma unroll
    for (int o = 16; o; o >>= 1) v += __shfl_xor_sync(0xffffffffu, v, o);
    if (lane == 0) wsum[warp] = v;
    __syncthreads();
    if (threadIdx.x == 0) {
        int s = 0;
        #pragma unroll
        for (int w = 0; w < NWARPS; w++) s += wsum[w];
        g_bsum[blockIdx.x] = s;
    }
}

// ---------------- scan phase 2: downsweep with redundant block-sum scan ----
__global__ void scan3_kernel() {
    __shared__ int wpre[NWARPS];
    __shared__ int bsc[SCAN_B];
    int t = threadIdx.x;
    // redundant scan of 196 block sums in every block (cheap)
    int bv = (t < SCAN_G) ? g_bsum[t] : 0;
    bsc[t] = bv;
    __syncthreads();
    for (int off = 1; off < SCAN_B; off <<= 1) {
        int add = (t >= off) ? bsc[t - off] : 0;
        __syncthreads();
        bsc[t] += add;
        __syncthreads();
    }
    int blockPre = (blockIdx.x == 0) ? 0 : bsc[blockIdx.x - 1];
    if (blockIdx.x == 0 && t == 0) g_offsets[NN] = ET;  // total is static

    int i = blockIdx.x * SCAN_B + t;
    int lane = t & 31;
    int warp = t >> 5;
    int c = (i < NN) ? g_count[i] : 0;
    int v = c;
    #pragma unroll
    for (int o = 1; o < 32; o <<= 1) {
        int u = __shfl_up_sync(0xffffffffu, v, o);
        if (lane >= o) v += u;
    }
    if (lane == 31) wpre[warp] = v;
    __syncthreads();
    if (warp == 0) {
        int u = (lane < NWARPS) ? wpre[lane] : 0;
        int s = u;
        #pragma unroll
        for (int o = 1; o < 32; o <<= 1) {
            int t2 = __shfl_up_sync(0xffffffffu, s, o);
            if (lane >= o) s += t2;
        }
        if (lane < NWARPS) wpre[lane] = s - u;
    }
    __syncthreads();
    if (i < NN) {
        int off = blockPre + wpre[warp] + (v - c);   // exclusive
        g_offsets[i] = off;
        g_cursor[i]  = off;
    }
}

// ---------------- scatter into CSR + precompute edge weights (packed) ----------------
__global__ void scatter_kernel() {
    int i = blockIdx.x * blockDim.x + threadIdx.x;
    if (i >= ET) return;
    int s, d;
    if (i < EE) { int2 sd = g_sd[i]; s = sd.x; d = sd.y; }
    else        { s = d = i - EE; }
    int pos = atomicAdd(&g_cursor[d], 1);
    float e = g_asrc[s] + g_adst[d];
    e = (e > 0.f) ? e : NEG_SLOPE * e;
    EW ew; ew.s = s; ew.w = __expf(e);
    g_ew[pos] = ew;                       // single STG.64
}

// ---------------- aggregate (packed weights) + ELU + fc fold ----------------
__global__ void aggregate_kernel(const float* __restrict__ bias,
                                 const float* __restrict__ fcw,
                                 const float* __restrict__ fcb) {
    int n    = (blockIdx.x * blockDim.x + threadIdx.x) >> 5;
    int lane = threadIdx.x & 31;
    if (n >= NN) return;
    int sub  = lane >> 4;        // 0/1: parity class of edges
    int l16  = lane & 15;        // column group

    int start = g_offsets[n];
    int end   = g_offsets[n + 1];

    float4 acc = make_float4(0.f, 0.f, 0.f, 0.f);
    float wsum = 0.f;
    int i = start + sub;
    for (; i + 2 < end; i += 4) {
        EW e0 = g_ew[i];
        EW e1 = g_ew[i + 2];
        float4 h0 = *(const float4*)&g_h[(long long)e0.s * HID + l16 * 4];
        float4 h1 = *(const float4*)&g_h[(long long)e1.s * HID + l16 * 4];
        wsum += e0.w + e1.w;
        acc.x = fmaf(e0.w, h0.x, fmaf(e1.w, h1.x, acc.x));
        acc.y = fmaf(e0.w, h0.y, fmaf(e1.w, h1.y, acc.y));
        acc.z = fmaf(e0.w, h0.z, fmaf(e1.w, h1.z, acc.z));
        acc.w = fmaf(e0.w, h0.w, fmaf(e1.w, h1.w, acc.w));
    }
    if (i < end) {
        EW e0 = g_ew[i];
        float4 h0 = *(const float4*)&g_h[(long long)e0.s * HID + l16 * 4];
        wsum += e0.w;
        acc.x = fmaf(e0.w, h0.x, acc.x);
        acc.y = fmaf(e0.w, h0.y, acc.y);
        acc.z = fmaf(e0.w, h0.z, acc.z);
        acc.w = fmaf(e0.w, h0.w, acc.w);
    }
    wsum += __shfl_xor_sync(0xffffffffu, wsum, 16);
    acc.x += __shfl_down_sync(0xffffffffu, acc.x, 16);
    acc.y += __shfl_down_sync(0xffffffffu, acc.y, 16);
    acc.z += __shfl_down_sync(0xffffffffu, acc.z, 16);
    acc.w += __shfl_down_sync(0xffffffffu, acc.w, 16);

    float inv = 1.0f / wsum;
    float4 b  = *(const float4*)&bias[l16 * 4];
    float o0 = acc.x * inv + b.x;
    float o1 = acc.y * inv + b.y;
    float o2 = acc.z * inv + b.z;
    float o3 = acc.w * inv + b.w;
    o0 = (o0 > 0.f) ? o0 : expm1f(o0);
    o1 = (o1 > 0.f) ? o1 : expm1f(o1);
    o2 = (o2 > 0.f) ? o2 : expm1f(o2);
    o3 = (o3 > 0.f) ? o3 : expm1f(o3);

    float4 f0 = *(const float4*)&fcw[l16 * 4];
    float4 f1 = *(const float4*)&fcw[HID + l16 * 4];
    float p0 = o0 * f0.x + o1 * f0.y + o2 * f0.z + o3 * f0.w;
    float p1 = o0 * f1.x + o1 * f1.y + o2 * f1.z + o3 * f1.w;
    #pragma unroll
    for (int o = 8; o; o >>= 1) {
        p0 += __shfl_xor_sync(0xffffffffu, p0, o);
        p1 += __shfl_xor_sync(0xffffffffu, p1, o);
    }
    if (lane == 0) {
        g_s0[n] = p0 + fcb[0];   // fold fc bias into s0
        g_s1[n] = p1;
    }
}

// ---------------- per-edge scores (4 edges per thread, packed pairs) ----------------
__global__ void score_kernel(float* __restrict__ out) {
    int t = blockIdx.x * blockDim.x + threadIdx.x;
    int e0 = t * 4;
    if (e0 >= EE) return;
    if (e0 + 4 <= EE) {
        int4 p01 = *(const int4*)&g_sd[e0];       // (s0,d0,s1,d1)
        int4 p23 = *(const int4*)&g_sd[e0 + 2];   // (s2,d2,s3,d3)
        float4 r;
        r.x = g_s0[p01.x] + g_s1[p01.y];
        r.y = g_s0[p01.z] + g_s1[p01.w];
        r.z = g_s0[p23.x] + g_s1[p23.y];
        r.w = g_s0[p23.z] + g_s1[p23.w];
        *(float4*)&out[e0] = r;
    } else {
        for (int e = e0; e < EE; e++) {
            int2 sd = g_sd[e];
            out[e] = g_s0[sd.x] + g_s1[sd.y];
        }
    }
}

// ---------------- launch ----------------
extern "C" void kernel_launch(void* const* d_in, const int* in_sizes, int n_in,
                              void* d_out, int out_size) {
    const float* x   = (const float*)d_in[0];
    const void*  ei  = d_in[1];
    const float* W   = (const float*)d_in[2];
    const float* asv = (const float*)d_in[3];
    const float* adv = (const float*)d_in[4];
    const float* bias= (const float*)d_in[5];
    const float* fcw = (const float*)d_in[6];
    const float* fcb = (const float*)d_in[7];
    float* out = (float*)d_out;

    init_kernel<<<(NN + 255) / 256, 256>>>((const int*)ei);
    gemm_kernel<<<(NN + GR - 1) / GR, 128>>>(x, W, asv, adv);
    edges_kernel<<<(EE + 255) / 256, 256>>>(ei);
    scan1_kernel<<<SCAN_G, SCAN_B>>>();
    scan3_kernel<<<SCAN_G, SCAN_B>>>();
    scatter_kernel<<<(ET + 255) / 256, 256>>>();
    aggregate_kernel<<<(NN * 32 + 255) / 256, 256>>>(bias, fcw, fcb);
    score_kernel<<<(EE / 4 + 255) / 256, 256>>>(out);
}